// round 6
// baseline (speedup 1.0000x reference)
#include <cuda_runtime.h>

#define Bn 16
#define Cn 64
#define Hn 256
#define Wn 256
#define CH_STRIDE (Hn * Wn)      // 65536 floats between channels

#define CHUNK  2                 // channels per pipeline stage
#define NITER  (Cn / CHUNK)      // 32
#define RS     38                // staged row slots
#define CS     44                // staged col slots (11 groups of 4)
#define NG     11
#define HALO   324               // 18*18 pooled halo
#define FCH    (RS * CS)         // 1672 floats per staged channel
#define BUFB   (CHUNK * FCH * 4) // bytes per double-buffer half

typedef unsigned long long u64;

// ---- f32x2 helpers -------------------------------------------------------
__device__ __forceinline__ void fma2(u64& d, u64 a, u64 b) {
    asm("fma.rn.f32x2 %0, %1, %2, %0;" : "+l"(d) : "l"(a), "l"(b));
}
__device__ __forceinline__ u64 bcast2(float v) {
    u64 r;
    asm("mov.b64 %0, {%1, %2};" : "=l"(r) : "f"(v), "f"(v));
    return r;
}
__device__ __forceinline__ float2 unpack2(u64 v) {
    float2 r;
    asm("mov.b64 {%0, %1}, %2;" : "=f"(r.x), "=f"(r.y) : "l"(v));
    return r;
}
__device__ __forceinline__ u64 as_u64(float2 v) {
    u64 r;
    asm("mov.b64 %0, {%1, %2};" : "=l"(r) : "f"(v.x), "f"(v.y));
    return r;
}

// ---- cp.async helpers ----------------------------------------------------
__device__ __forceinline__ void cp_async16(unsigned int smem_dst, const float* src) {
    asm volatile("cp.async.cg.shared.global [%0], [%1], 16;" :: "r"(smem_dst), "l"(src));
}
__device__ __forceinline__ void cp_commit() { asm volatile("cp.async.commit_group;"); }
__device__ __forceinline__ void cp_wait0()  { asm volatile("cp.async.wait_group 0;"); }

// ---------------------------------------------------------------------------
// Fully fused: block = 32x32 output tile (16x16 quads).
// Per 2-channel chunk (double-buffered cp.async):
//   stage a 38x44 feature slot-tile covering quad region + pooling inputs,
//   compute 18x18 pooled halo in smem (+ P2 fold), then quad accumulation.
// Slot maps (built once per block) handle jnp.roll wrap (mod 128 in pooled
// space -> wrapped feature rows/cols get their own slot runs) and avg-pool
// zero padding (row/col -1 -> dedicated slots zeroed each chunk).
// ---------------------------------------------------------------------------
__global__ __launch_bounds__(256, 4) void fused_kernel(const float* __restrict__ feat,
                                                       float* __restrict__ out) {
    __shared__ __align__(16) float sfeat[2][CHUNK][FCH];   // 26,752 B
    __shared__ float shalo[CHUNK][HALO];                   //  2,592 B
    __shared__ float sP2[HALO];                            //  1,296 B
    __shared__ int m_srow[RS];      // feature row per slot (-1 pad, -2 unused)
    __shared__ int m_rb[18];        // row-slot base per halo row
    __shared__ int m_gsrc[NG];      // source col per 4-col group (-1 skip)
    __shared__ int m_cslot[18];     // col slot of col 2gc-1 per halo col
    __shared__ int m_misc[2];       // pad row slot, pad col slot

    int b   = blockIdx.z;
    int ph0 = blockIdx.y << 4;
    int pw0 = blockIdx.x << 4;
    int tid = threadIdx.x;
    int qx  = tid & 15, qy = tid >> 4;

    // ---- build slot maps (thread 0) ----
    if (tid == 0) {
        int ns = 0, padr = -1;
        for (int i = 0; i < 18; i++) {
            int gr = (ph0 - 1 + i) & 127;
#pragma unroll
            for (int t = 0; t < 3; t++) {
                int r = 2 * gr + t - 1;
                if (ns > 0 && m_srow[ns - 1] == r) {
                    if (t == 0) m_rb[i] = ns - 1;
                } else {
                    m_srow[ns] = r;
                    if (t == 0) m_rb[i] = ns;
                    if (r < 0) padr = ns;
                    ns++;
                }
            }
        }
        for (int s = ns; s < RS; s++) m_srow[s] = -2;

        for (int g = 0; g < NG; g++) m_gsrc[g] = -1;
        int prevc = -1000000, curslot = -1, run_c0al = 0, run_base = 0, padc = -1;
        for (int j = 0; j < 18; j++) {
            int gc = (pw0 - 1 + j) & 127;
#pragma unroll
            for (int t = 0; t < 3; t++) {
                int c = 2 * gc + t - 1;
                if (c == prevc) {
                    // dedup with previous col: slot unchanged
                } else if (c == prevc + 1) {
                    curslot++;
                } else {
                    run_base = (curslot + 4) & ~3;
                    run_c0al = c & ~3;          // works for c=-1 -> -4
                    curslot  = run_base + (c - run_c0al);
                }
                prevc = c;
                if (t == 0) m_cslot[j] = curslot;
                if (c < 0) padc = curslot;
                int src = run_c0al + ((curslot - run_base) & ~3);
                m_gsrc[curslot >> 2] = (src >= 0) ? src : -1;
            }
        }
        m_misc[0] = padr;
        m_misc[1] = padc;
    }
    __syncthreads();

    const float* fimg = feat + (size_t)b * Cn * CH_STRIDE;
    unsigned int sfeat_a = (unsigned int)__cvta_generic_to_shared(&sfeat[0][0][0]);

    // ---- per-thread staging descriptors (4 cp16 slots) ----
    int d_src[4], d_dst[4];
#pragma unroll
    for (int u = 0; u < 4; u++) {
        int k = tid + 256 * u;
        d_src[u] = -1;
        if (k < RS * NG * CHUNK) {
            int c  = k / (RS * NG);
            int r2 = k - c * (RS * NG);
            int s  = r2 / NG;
            int g  = r2 - s * NG;
            if (m_srow[s] >= 0 && m_gsrc[g] >= 0) {
                d_src[u] = c * CH_STRIDE + m_srow[s] * Wn + m_gsrc[g];
                d_dst[u] = ((c * RS + s) * CS + 4 * g) * 4;
            }
        }
    }
    int padr = m_misc[0], padc = m_misc[1];

    // pooling cell assignments: cell0 = tid (always), cell1 = tid+256 (tid<68)
    int i0 = tid / 18, j0 = tid - i0 * 18;
    int poff0 = m_rb[i0] * CS + m_cslot[j0];
    int cell1 = tid + 256;
    bool has1 = (cell1 < HALO);
    int poff1 = 0;
    if (has1) {
        int i1 = cell1 / 18, j1 = cell1 - i1 * 18;
        poff1 = m_rb[i1] * CS + m_cslot[j1];
    }
    // quad offsets: feature rows 2gr,2gr+1 -> rb[qy+1]+1,+2; cols analogous
    int qoff  = (m_rb[qy + 1] + 1) * CS + (m_cslot[qx + 1] + 1);
    int sbase = (qy + 1) * 18 + (qx + 1);

    auto stage = [&](int buf, int cc) {
        const float* base = fimg + (size_t)cc * CH_STRIDE;
#pragma unroll
        for (int u = 0; u < 4; u++)
            if (d_src[u] >= 0)
                cp_async16(sfeat_a + buf * BUFB + d_dst[u], base + d_src[u]);
        cp_commit();
    };

    u64 z = 0;
    u64 cr01[8], cr23[8];
#pragma unroll
    for (int s = 0; s < 8; s++) { cr01[s] = z; cr23[s] = z; }
    u64 F2_01 = z, F2_23 = z;
    const float inv9 = 1.0f / 9.0f;

    stage(0, 0);

    for (int it = 0; it < NITER; it++) {
        int cur = it & 1;
        cp_wait0();
        // zero-fix pad slots in current buffer (slots cp.async never writes)
        if (padr >= 0 && tid < CS * CHUNK) {
            int c = tid / CS, col = tid - c * CS;
            sfeat[cur][c][padr * CS + col] = 0.f;
        }
        if (padc >= 0 && tid < RS * CHUNK) {
            int c = tid / RS, r = tid - c * RS;
            sfeat[cur][c][r * CS + padc] = 0.f;
        }
        __syncthreads();   // A: staged+fixed data visible; prev quad reads done

        if (it + 1 < NITER) stage(1 - cur, (it + 1) * CHUNK);

        // ---- pooling into shalo + P2 fold (thread-owned cells) ----
        {
            float acc = (it == 0) ? 0.f : sP2[tid];
#pragma unroll
            for (int c = 0; c < CHUNK; c++) {
                const float* fb = &sfeat[cur][c][0];
                float v = fb[poff0] + fb[poff0 + 1] + fb[poff0 + 2]
                        + fb[poff0 + CS] + fb[poff0 + CS + 1] + fb[poff0 + CS + 2]
                        + fb[poff0 + 2 * CS] + fb[poff0 + 2 * CS + 1] + fb[poff0 + 2 * CS + 2];
                v *= inv9;
                shalo[c][tid] = v;
                acc += v * v;
            }
            sP2[tid] = acc;
            if (has1) {
                float acc1 = (it == 0) ? 0.f : sP2[cell1];
#pragma unroll
                for (int c = 0; c < CHUNK; c++) {
                    const float* fb = &sfeat[cur][c][0];
                    float v = fb[poff1] + fb[poff1 + 1] + fb[poff1 + 2]
                            + fb[poff1 + CS] + fb[poff1 + CS + 1] + fb[poff1 + CS + 2]
                            + fb[poff1 + 2 * CS] + fb[poff1 + 2 * CS + 1] + fb[poff1 + 2 * CS + 2];
                    v *= inv9;
                    shalo[c][cell1] = v;
                    acc1 += v * v;
                }
                sP2[cell1] = acc1;
            }
        }
        __syncthreads();   // B: halo ready

        // ---- quad accumulation (all operands from smem) ----
#pragma unroll
        for (int c = 0; c < CHUNK; c++) {
            const float* fb = &sfeat[cur][c][0];
            u64 f01 = as_u64(*reinterpret_cast<const float2*>(fb + qoff));
            u64 f23 = as_u64(*reinterpret_cast<const float2*>(fb + qoff + CS));

            const float* hc = &shalo[c][0];
            float ps[8];
            ps[0] = hc[sbase - 19]; ps[1] = hc[sbase - 18]; ps[2] = hc[sbase - 17];
            ps[3] = hc[sbase - 1];                          ps[4] = hc[sbase + 1];
            ps[5] = hc[sbase + 17]; ps[6] = hc[sbase + 18]; ps[7] = hc[sbase + 19];

            fma2(F2_01, f01, f01);
            fma2(F2_23, f23, f23);
#pragma unroll
            for (int s = 0; s < 8; s++) {
                u64 pp = bcast2(ps[s]);
                fma2(cr01[s], f01, pp);
                fma2(cr23[s], f23, pp);
            }
        }
    }

    // ---- P2 at the 8 neighbors ----
    float P2n[8];
    P2n[0] = sP2[sbase - 19]; P2n[1] = sP2[sbase - 18]; P2n[2] = sP2[sbase - 17];
    P2n[3] = sP2[sbase - 1];                             P2n[4] = sP2[sbase + 1];
    P2n[5] = sP2[sbase + 17]; P2n[6] = sP2[sbase + 18]; P2n[7] = sP2[sbase + 19];

    float2 F2p01 = unpack2(F2_01);
    float2 F2p23 = unpack2(F2_23);
    float F2arr[4] = {F2p01.x, F2p01.y, F2p23.x, F2p23.y};

    float res[4] = {-3.4e38f, -3.4e38f, -3.4e38f, -3.4e38f};
#pragma unroll
    for (int s = 0; s < 8; s++) {
        float2 c01 = unpack2(cr01[s]);
        float2 c23 = unpack2(cr23[s]);
        res[0] = fmaxf(res[0], F2arr[0] - 2.f * c01.x + P2n[s]);
        res[1] = fmaxf(res[1], F2arr[1] - 2.f * c01.y + P2n[s]);
        res[2] = fmaxf(res[2], F2arr[2] - 2.f * c23.x + P2n[s]);
        res[3] = fmaxf(res[3], F2arr[3] - 2.f * c23.y + P2n[s]);
    }

    int ph = ph0 + qy, pw = pw0 + qx;
    float* orow = out + (size_t)b * (Hn * Wn) + (ph << 1) * Wn + (pw << 1);
    *reinterpret_cast<float2*>(orow)      = make_float2(res[0], res[1]);
    *reinterpret_cast<float2*>(orow + Wn) = make_float2(res[2], res[3]);
}

// ---------------------------------------------------------------------------
extern "C" void kernel_launch(void* const* d_in, const int* in_sizes, int n_in,
                              void* d_out, int out_size) {
    const float* feat = (const float*)d_in[0];
    float* out = (float*)d_out;
    // dist is fixed at 1 by the problem's setup_inputs (d = 2)

    dim3 g(8, 8, Bn);
    fused_kernel<<<g, 256>>>(feat, out);
}

// round 8
// speedup vs baseline: 1.4474x; 1.4474x over previous
#include <cuda_runtime.h>

#define Bn 16
#define Cn 64
#define Hn 256
#define Wn 256
#define PHn 128
#define PWn 128
#define CH_STRIDE (Hn * Wn)      // 65536 floats between channels (feature)
#define PCH_STRIDE (PHn * PWn)   // 16384 floats between channels (pooled)

typedef unsigned long long u64;

// scratch (static __device__ — allocation-free per harness rules)
__device__ float g_pooled[Bn * Cn * PHn * PWn];  // 64 MiB

// ---- f32x2 helpers -------------------------------------------------------
__device__ __forceinline__ void fma2(u64& d, u64 a, u64 b) {
    asm("fma.rn.f32x2 %0, %1, %2, %0;" : "+l"(d) : "l"(a), "l"(b));
}
__device__ __forceinline__ u64 bcast2(float v) {
    u64 r;
    asm("mov.b64 %0, {%1, %2};" : "=l"(r) : "f"(v), "f"(v));
    return r;
}
__device__ __forceinline__ float2 unpack2(u64 v) {
    float2 r;
    asm("mov.b64 {%0, %1}, %2;" : "=f"(r.x), "=f"(r.y) : "l"(v));
    return r;
}
__device__ __forceinline__ u64 as_u64(float2 v) {
    u64 r;
    asm("mov.b64 %0, {%1, %2};" : "=l"(r) : "f"(v.x), "f"(v.y));
    return r;
}

// ---- cp.async helpers ----------------------------------------------------
__device__ __forceinline__ void cp_async4(unsigned int smem_dst, const float* src) {
    asm volatile("cp.async.ca.shared.global [%0], [%1], 4;" :: "r"(smem_dst), "l"(src));
}
__device__ __forceinline__ void cp_async16(unsigned int smem_dst, const float* src) {
    asm volatile("cp.async.cg.shared.global [%0], [%1], 16;" :: "r"(smem_dst), "l"(src));
}
__device__ __forceinline__ void cp_commit() { asm volatile("cp.async.commit_group;"); }
__device__ __forceinline__ void cp_wait0()  { asm volatile("cp.async.wait_group 0;"); }

// ---------------------------------------------------------------------------
// Pass 1: avg_pool2d k=3 s=2 pad=1 (count_include_pad: always /9).
// 84% DRAM — near unique-traffic roofline; unchanged.
// ---------------------------------------------------------------------------
__global__ __launch_bounds__(256) void pool_kernel(const float* __restrict__ feat) {
    int idx = blockIdx.x * 256 + threadIdx.x;
    int pwq = idx & 31;
    int t   = idx >> 5;
    int ph  = t & 127;
    int bc  = t >> 7;
    const float* src = feat + (size_t)bc * (Hn * Wn);
    int c0 = pwq << 3;

    float s0 = 0.f, s1 = 0.f, s2 = 0.f, s3 = 0.f;
    int rbase = 2 * ph - 1;
#pragma unroll
    for (int rr = 0; rr < 3; rr++) {
        int r = rbase + rr;
        if (r < 0) continue;
        const float* row = src + r * Wn;
        float left = (c0 > 0) ? __ldcs(row + c0 - 1) : 0.f;
        float4 a  = __ldcs(reinterpret_cast<const float4*>(row + c0));
        float4 b4 = __ldcs(reinterpret_cast<const float4*>(row + c0 + 4));
        s0 += left + a.x  + a.y;
        s1 += a.y  + a.z  + a.w;
        s2 += a.w  + b4.x + b4.y;
        s3 += b4.y + b4.z + b4.w;
    }
    const float inv9 = 1.0f / 9.0f;
    float4 o = make_float4(s0 * inv9, s1 * inv9, s2 * inv9, s3 * inv9);
    *reinterpret_cast<float4*>(g_pooled + (size_t)bc * PCH_STRIDE + ph * PWn + (pwq << 2)) = o;
}

// ---------------------------------------------------------------------------
// Pass 2: diff + fused P2. Block = 16x16 quads = 32x32 output tile.
// Pooled halo staged as row-aligned 18x24 slabs (stride 28) via cp.async16,
// 8 channels per double-buffered stage. jnp.roll column wrap (pw0==0 / 112)
// patched via one scalar cp.async4 per row into slab col 24 — a slot the
// bulk cp16 staging (cols 0..23) never writes (fixes R7 write collision).
// Feature read directly via batched __ldcs LDG.64 (no smem round trip).
// Math in f32x2 packed pairs.
// ---------------------------------------------------------------------------
#define CHUNKH 8
#define HALO   324                 // 18*18 (dense index space for sP2)
#define SSTR   28                  // slab row stride (floats, 112B: 16B-aligned)
#define SLAB   (18 * SSTR)         // 504 floats per channel slab
#define NITER  (Cn / CHUNKH)       // 8
#define WSLOT  24                  // wrap-column slab slot (outside cp16 range)

__global__ __launch_bounds__(256, 4) void diff_kernel(const float* __restrict__ feat,
                                                      float* __restrict__ out) {
    __shared__ __align__(16) float shalo[2][CHUNKH * SLAB];  // 32,256 B
    __shared__ float sP2[HALO];                              //  1,296 B

    int b   = blockIdx.z;
    int ph0 = blockIdx.y << 4;
    int pw0 = blockIdx.x << 4;
    int tid = threadIdx.x;
    int qx  = tid & 15, qy = tid >> 4;

    // ---- block-uniform column-map parameters ----
    int  cbase = (pw0 == 0) ? 0 : ((pw0 == 112) ? 104 : (pw0 - 4));
    bool wrap  = (pw0 == 0) || (pw0 == 112);
    int  wsrc  = (pw0 == 0) ? 127 : 0;    // wrapped gmem col

    // slab column for halo col j (pooled col (pw0-1+j)&127)
    auto scol = [&](int j) -> int {
        if (pw0 == 0)   return (j == 0)  ? WSLOT : (j - 1);
        if (pw0 == 112) return (j == 17) ? WSLOT : (7 + j);
        return j + 3;
    };

    const float* fimg = feat + (size_t)b * Cn * CH_STRIDE;
    const float* pimg = g_pooled + (size_t)b * Cn * PCH_STRIDE;
    unsigned int shalo_a = (unsigned int)__cvta_generic_to_shared(&shalo[0][0]);

    // ---- staging: 8 channels of the pooled halo slab ----
    auto stage = [&](int buf, int cc) {
        unsigned int dbase = shalo_a + buf * (CHUNKH * SLAB * 4);
        const float* sbase_p = pimg + (size_t)cc * PCH_STRIDE + cbase;
#pragma unroll
        for (int u = 0; u < 4; u++) {
            int k = tid + 256 * u;
            if (k < CHUNKH * 108) {             // 18 rows x 6 groups per channel
                int c   = k / 108;
                int rem = k - 108 * c;
                int row = rem / 6;
                int g   = rem - 6 * row;
                int gr  = (ph0 - 1 + row) & 127;
                cp_async16(dbase + (unsigned)((c * SLAB) + row * SSTR + 4 * g) * 4,
                           sbase_p + (size_t)c * PCH_STRIDE + gr * PWn + 4 * g);
            }
        }
        if (wrap && tid < CHUNKH * 18) {
            int c   = tid / 18;
            int row = tid - 18 * c;
            int gr  = (ph0 - 1 + row) & 127;
            cp_async4(dbase + (unsigned)((c * SLAB) + row * SSTR + WSLOT) * 4,
                      pimg + (size_t)(cc + c) * PCH_STRIDE + gr * PWn + wsrc);
        }
        cp_commit();
    };

    // ---- per-thread consumer offsets ----
    int i0 = tid / 18, j0 = tid - i0 * 18;
    int off0 = i0 * SSTR + scol(j0);            // P2 cell 0 slab offset
    int cell1 = tid + 256;
    bool has1 = (cell1 < HALO);
    int off1 = 0;
    if (has1) {
        int i1 = cell1 / 18, j1 = cell1 - i1 * 18;
        off1 = i1 * SSTR + scol(j1);
    }
    int rA = qy * SSTR, rB = rA + SSTR, rC = rB + SSTR;
    int c0 = scol(qx), c1 = scol(qx + 1), c2 = scol(qx + 2);
    int sbase = (qy + 1) * 18 + (qx + 1);       // dense sP2 index
    const float* fbase = fimg + (size_t)((ph0 + qy) << 1) * Wn + ((pw0 + qx) << 1);

    u64 z = 0;
    u64 cr01[8], cr23[8];
#pragma unroll
    for (int s = 0; s < 8; s++) { cr01[s] = z; cr23[s] = z; }
    u64 F2_01 = z, F2_23 = z;

    stage(0, 0);

    for (int it = 0; it < NITER; it++) {
        int cur = it & 1;
        cp_wait0();
        __syncthreads();                        // staged chunk visible; prev reads done
        if (it + 1 < NITER) stage(1 - cur, (it + 1) * CHUNKH);

        const float* hbuf = &shalo[cur][0];

        // ---- fold P2 over the staged slabs (thread-owned cells) ----
        {
            float acc0 = (it == 0) ? 0.f : sP2[tid];
#pragma unroll
            for (int c = 0; c < CHUNKH; c++) {
                float v = hbuf[c * SLAB + off0];
                acc0 += v * v;
            }
            sP2[tid] = acc0;
            if (has1) {
                float acc1 = (it == 0) ? 0.f : sP2[cell1];
#pragma unroll
                for (int c = 0; c < CHUNKH; c++) {
                    float v = hbuf[c * SLAB + off1];
                    acc1 += v * v;
                }
                sP2[cell1] = acc1;
            }
        }

        // ---- quad accumulation: 2 groups of 4 channels, direct LDG batches ----
#pragma unroll
        for (int g = 0; g < 2; g++) {
            float2 fa[4], fb[4];
            const float* fp = fbase + (size_t)(it * CHUNKH + g * 4) * CH_STRIDE;
#pragma unroll
            for (int t = 0; t < 4; t++) {
                fa[t] = __ldcs(reinterpret_cast<const float2*>(fp));
                fb[t] = __ldcs(reinterpret_cast<const float2*>(fp + Wn));
                fp += CH_STRIDE;
            }
#pragma unroll
            for (int t = 0; t < 4; t++) {
                const float* hc = hbuf + (g * 4 + t) * SLAB;
                float ps[8];
                ps[0] = hc[rA + c0]; ps[1] = hc[rA + c1]; ps[2] = hc[rA + c2];
                ps[3] = hc[rB + c0];                      ps[4] = hc[rB + c2];
                ps[5] = hc[rC + c0]; ps[6] = hc[rC + c1]; ps[7] = hc[rC + c2];

                u64 f01 = as_u64(fa[t]);
                u64 f23 = as_u64(fb[t]);
                fma2(F2_01, f01, f01);
                fma2(F2_23, f23, f23);
#pragma unroll
                for (int s = 0; s < 8; s++) {
                    u64 pp = bcast2(ps[s]);
                    fma2(cr01[s], f01, pp);
                    fma2(cr23[s], f23, pp);
                }
            }
        }
    }
    __syncthreads();   // sP2 fully accumulated and visible

    // ---- P2 at the 8 neighbors (dense sP2 tile) ----
    float P2n[8];
    P2n[0] = sP2[sbase - 19]; P2n[1] = sP2[sbase - 18]; P2n[2] = sP2[sbase - 17];
    P2n[3] = sP2[sbase - 1];                             P2n[4] = sP2[sbase + 1];
    P2n[5] = sP2[sbase + 17]; P2n[6] = sP2[sbase + 18]; P2n[7] = sP2[sbase + 19];

    float2 F2p01 = unpack2(F2_01);
    float2 F2p23 = unpack2(F2_23);
    float F2arr[4] = {F2p01.x, F2p01.y, F2p23.x, F2p23.y};

    float res[4] = {-3.4e38f, -3.4e38f, -3.4e38f, -3.4e38f};
#pragma unroll
    for (int s = 0; s < 8; s++) {
        float2 c01 = unpack2(cr01[s]);
        float2 c23 = unpack2(cr23[s]);
        res[0] = fmaxf(res[0], F2arr[0] - 2.f * c01.x + P2n[s]);
        res[1] = fmaxf(res[1], F2arr[1] - 2.f * c01.y + P2n[s]);
        res[2] = fmaxf(res[2], F2arr[2] - 2.f * c23.x + P2n[s]);
        res[3] = fmaxf(res[3], F2arr[3] - 2.f * c23.y + P2n[s]);
    }

    int ph = ph0 + qy, pw = pw0 + qx;
    float* orow = out + (size_t)b * (Hn * Wn) + (ph << 1) * Wn + (pw << 1);
    *reinterpret_cast<float2*>(orow)      = make_float2(res[0], res[1]);
    *reinterpret_cast<float2*>(orow + Wn) = make_float2(res[2], res[3]);
}

// ---------------------------------------------------------------------------
extern "C" void kernel_launch(void* const* d_in, const int* in_sizes, int n_in,
                              void* d_out, int out_size) {
    const float* feat = (const float*)d_in[0];
    float* out = (float*)d_out;
    // dist is fixed at 1 by the problem's setup_inputs (d = 2)

    pool_kernel<<<16384, 256>>>(feat);
    dim3 g(8, 8, Bn);
    diff_kernel<<<g, 256>>>(feat, out);
}

// round 9
// speedup vs baseline: 1.7352x; 1.1988x over previous
#include <cuda_runtime.h>

#define Bn 16
#define Cn 64
#define Hn 256
#define Wn 256
#define PHn 128
#define PWn 128
#define CH_STRIDE (Hn * Wn)      // 65536 floats between channels (feature)
#define PCH_STRIDE (PHn * PWn)   // 16384 floats between channels (pooled)

typedef unsigned long long u64;

// scratch (static __device__ — allocation-free per harness rules)
__device__ float g_pooled[Bn * Cn * PHn * PWn];  // 64 MiB

// ---- f32x2 helpers -------------------------------------------------------
__device__ __forceinline__ void fma2(u64& d, u64 a, u64 b) {
    asm("fma.rn.f32x2 %0, %1, %2, %0;" : "+l"(d) : "l"(a), "l"(b));
}
__device__ __forceinline__ u64 bcast2(float v) {
    u64 r;
    asm("mov.b64 %0, {%1, %2};" : "=l"(r) : "f"(v), "f"(v));
    return r;
}
__device__ __forceinline__ float2 unpack2(u64 v) {
    float2 r;
    asm("mov.b64 {%0, %1}, %2;" : "=f"(r.x), "=f"(r.y) : "l"(v));
    return r;
}
__device__ __forceinline__ u64 as_u64(float2 v) {
    u64 r;
    asm("mov.b64 %0, {%1, %2};" : "=l"(r) : "f"(v.x), "f"(v.y));
    return r;
}

// ---- cp.async helpers ----------------------------------------------------
__device__ __forceinline__ void cp_async4(unsigned int smem_dst, const float* src) {
    asm volatile("cp.async.ca.shared.global [%0], [%1], 4;" :: "r"(smem_dst), "l"(src));
}
__device__ __forceinline__ void cp_async16(unsigned int smem_dst, const float* src) {
    asm volatile("cp.async.cg.shared.global [%0], [%1], 16;" :: "r"(smem_dst), "l"(src));
}
__device__ __forceinline__ void cp_commit() { asm volatile("cp.async.commit_group;"); }
__device__ __forceinline__ void cp_wait0()  { asm volatile("cp.async.wait_group 0;"); }

// ---------------------------------------------------------------------------
// Pass 1: avg_pool2d k=3 s=2 pad=1 (count_include_pad: always /9).
// 84% DRAM — near unique-traffic roofline; unchanged.
// ---------------------------------------------------------------------------
__global__ __launch_bounds__(256) void pool_kernel(const float* __restrict__ feat) {
    int idx = blockIdx.x * 256 + threadIdx.x;
    int pwq = idx & 31;
    int t   = idx >> 5;
    int ph  = t & 127;
    int bc  = t >> 7;
    const float* src = feat + (size_t)bc * (Hn * Wn);
    int c0 = pwq << 3;

    float s0 = 0.f, s1 = 0.f, s2 = 0.f, s3 = 0.f;
    int rbase = 2 * ph - 1;
#pragma unroll
    for (int rr = 0; rr < 3; rr++) {
        int r = rbase + rr;
        if (r < 0) continue;
        const float* row = src + r * Wn;
        float left = (c0 > 0) ? __ldcs(row + c0 - 1) : 0.f;
        float4 a  = __ldcs(reinterpret_cast<const float4*>(row + c0));
        float4 b4 = __ldcs(reinterpret_cast<const float4*>(row + c0 + 4));
        s0 += left + a.x  + a.y;
        s1 += a.y  + a.z  + a.w;
        s2 += a.w  + b4.x + b4.y;
        s3 += b4.y + b4.z + b4.w;
    }
    const float inv9 = 1.0f / 9.0f;
    float4 o = make_float4(s0 * inv9, s1 * inv9, s2 * inv9, s3 * inv9);
    *reinterpret_cast<float4*>(g_pooled + (size_t)bc * PCH_STRIDE + ph * PWn + (pwq << 2)) = o;
}

// ---------------------------------------------------------------------------
// Pass 2: diff + fused P2. Block = 16x16 quads = 32x32 output tile.
// Per 4-channel double-buffered cp.async stage:
//   - feature 32x32 tile (unpadded, cp16, conflict-free LDS.64 reads)
//   - pooled halo as 18x24 slab (stride 28, cp16) + wrap col in slot 24 (cp4)
// P2 fold carried in REGISTERS (thread owns halo cells tid / tid+256);
// final 18x18 sP2 tile written into reused shalo smem after the loop.
// Math in f32x2 packed pairs.
// ---------------------------------------------------------------------------
#define CHUNK  4
#define HALO   324                 // 18*18 (dense index space for sP2)
#define SSTR   28                  // slab row stride (floats, 112B: 16B-aligned)
#define SLAB   (18 * SSTR)         // 504 floats per channel slab
#define FROW   32                  // feature smem row (floats, unpadded)
#define FCH    (32 * FROW)         // 1024 floats per staged channel
#define NITER  (Cn / CHUNK)        // 16
#define WSLOT  24                  // wrap-column slab slot (outside cp16 range)

__global__ __launch_bounds__(256, 4) void diff_kernel(const float* __restrict__ feat,
                                                      float* __restrict__ out) {
    __shared__ __align__(16) float sfeat[2][CHUNK * FCH];   // 32,768 B
    __shared__ __align__(16) float shalo[2][CHUNK * SLAB];  // 16,128 B
    // total 48,896 B; sP2 aliases shalo[0] after the loop

    int b   = blockIdx.z;
    int ph0 = blockIdx.y << 4;
    int pw0 = blockIdx.x << 4;
    int tid = threadIdx.x;
    int qx  = tid & 15, qy = tid >> 4;

    // ---- block-uniform column-map parameters ----
    int  cbase = (pw0 == 0) ? 0 : ((pw0 == 112) ? 104 : (pw0 - 4));
    bool wrap  = (pw0 == 0) || (pw0 == 112);
    int  wsrc  = (pw0 == 0) ? 127 : 0;    // wrapped gmem col

    // slab column for halo col j (pooled col (pw0-1+j)&127)
    auto scol = [&](int j) -> int {
        if (pw0 == 0)   return (j == 0)  ? WSLOT : (j - 1);
        if (pw0 == 112) return (j == 17) ? WSLOT : (7 + j);
        return j + 3;
    };

    const float* fimg = feat + (size_t)b * Cn * CH_STRIDE;
    const float* pimg = g_pooled + (size_t)b * Cn * PCH_STRIDE;
    unsigned int sfeat_a = (unsigned int)__cvta_generic_to_shared(&sfeat[0][0]);
    unsigned int shalo_a = (unsigned int)__cvta_generic_to_shared(&shalo[0][0]);

    // ---- feature staging constants: 1 cp16 per channel per thread ----
    int frow = tid >> 3;
    int fcol = (tid & 7) << 2;
    const float* fsrc0 = fimg + (size_t)((ph0 << 1) + frow) * Wn + (pw0 << 1) + fcol;
    unsigned int fdst0 = sfeat_a + (unsigned)(frow * FROW + fcol) * 4;

    // ---- staging: one 4-channel chunk (feature tile + halo slab) ----
    auto stage = [&](int buf, int cc) {
        unsigned int fd = fdst0 + buf * (CHUNK * FCH * 4);
        const float* fs = fsrc0 + (size_t)cc * CH_STRIDE;
#pragma unroll
        for (int m = 0; m < CHUNK; m++) {
            cp_async16(fd + m * (FCH * 4), fs);
            fs += CH_STRIDE;
        }
        unsigned int dbase = shalo_a + buf * (CHUNK * SLAB * 4);
        const float* sbase_p = pimg + (size_t)cc * PCH_STRIDE + cbase;
#pragma unroll
        for (int u = 0; u < 2; u++) {
            int k = tid + 256 * u;
            if (k < CHUNK * 108) {              // 18 rows x 6 groups per channel
                int c   = k / 108;
                int rem = k - 108 * c;
                int row = rem / 6;
                int g   = rem - 6 * row;
                int gr  = (ph0 - 1 + row) & 127;
                cp_async16(dbase + (unsigned)((c * SLAB) + row * SSTR + 4 * g) * 4,
                           sbase_p + (size_t)c * PCH_STRIDE + gr * PWn + 4 * g);
            }
        }
        if (wrap && tid < CHUNK * 18) {
            int c   = tid / 18;
            int row = tid - 18 * c;
            int gr  = (ph0 - 1 + row) & 127;
            cp_async4(dbase + (unsigned)((c * SLAB) + row * SSTR + WSLOT) * 4,
                      pimg + (size_t)(cc + c) * PCH_STRIDE + gr * PWn + wsrc);
        }
        cp_commit();
    };

    // ---- per-thread P2 cell offsets (fold carried in registers) ----
    int i0 = tid / 18, j0 = tid - i0 * 18;
    int off0 = i0 * SSTR + scol(j0);
    int cell1 = tid + 256;
    bool has1 = (cell1 < HALO);
    int off1 = 0;
    if (has1) {
        int i1 = cell1 / 18, j1 = cell1 - i1 * 18;
        off1 = i1 * SSTR + scol(j1);
    }
    float p2acc0 = 0.f, p2acc1 = 0.f;

    // ---- quad consumer offsets ----
    int rA = qy * SSTR, rB = rA + SSTR, rC = rB + SSTR;
    int c0 = scol(qx), c1 = scol(qx + 1), c2 = scol(qx + 2);
    int sbase = (qy + 1) * 18 + (qx + 1);       // dense sP2 index
    int qoff  = (qy << 1) * FROW + (qx << 1);

    u64 z = 0;
    u64 cr01[8], cr23[8];
#pragma unroll
    for (int s = 0; s < 8; s++) { cr01[s] = z; cr23[s] = z; }
    u64 F2_01 = z, F2_23 = z;

    stage(0, 0);

    for (int it = 0; it < NITER; it++) {
        int cur = it & 1;
        cp_wait0();
        __syncthreads();                        // staged chunk visible; prev reads done
        if (it + 1 < NITER) stage(1 - cur, (it + 1) * CHUNK);

        const float* hbuf = &shalo[cur][0];
        const float* fbuf = &sfeat[cur][0];

        // ---- P2 fold over the staged slabs (registers, no smem round trip)
#pragma unroll
        for (int c = 0; c < CHUNK; c++) {
            float v0 = hbuf[c * SLAB + off0];
            p2acc0 += v0 * v0;
        }
        if (has1) {
#pragma unroll
            for (int c = 0; c < CHUNK; c++) {
                float v1 = hbuf[c * SLAB + off1];
                p2acc1 += v1 * v1;
            }
        }

        // ---- quad accumulation (all operands from smem)
#pragma unroll
        for (int c = 0; c < CHUNK; c++) {
            const float* fp = fbuf + c * FCH + qoff;
            u64 f01 = as_u64(*reinterpret_cast<const float2*>(fp));
            u64 f23 = as_u64(*reinterpret_cast<const float2*>(fp + FROW));

            const float* hc = hbuf + c * SLAB;
            float ps[8];
            ps[0] = hc[rA + c0]; ps[1] = hc[rA + c1]; ps[2] = hc[rA + c2];
            ps[3] = hc[rB + c0];                      ps[4] = hc[rB + c2];
            ps[5] = hc[rC + c0]; ps[6] = hc[rC + c1]; ps[7] = hc[rC + c2];

            fma2(F2_01, f01, f01);
            fma2(F2_23, f23, f23);
#pragma unroll
            for (int s = 0; s < 8; s++) {
                u64 pp = bcast2(ps[s]);
                fma2(cr01[s], f01, pp);
                fma2(cr23[s], f23, pp);
            }
        }
    }

    // ---- publish P2 tile into reused smem (shalo buffer 0) ----
    __syncthreads();                            // all halo reads complete
    float* sP2 = &shalo[0][0];
    sP2[tid] = p2acc0;
    if (has1) sP2[cell1] = p2acc1;
    __syncthreads();

    float P2n[8];
    P2n[0] = sP2[sbase - 19]; P2n[1] = sP2[sbase - 18]; P2n[2] = sP2[sbase - 17];
    P2n[3] = sP2[sbase - 1];                             P2n[4] = sP2[sbase + 1];
    P2n[5] = sP2[sbase + 17]; P2n[6] = sP2[sbase + 18]; P2n[7] = sP2[sbase + 19];

    float2 F2p01 = unpack2(F2_01);
    float2 F2p23 = unpack2(F2_23);
    float F2arr[4] = {F2p01.x, F2p01.y, F2p23.x, F2p23.y};

    float res[4] = {-3.4e38f, -3.4e38f, -3.4e38f, -3.4e38f};
#pragma unroll
    for (int s = 0; s < 8; s++) {
        float2 c01 = unpack2(cr01[s]);
        float2 c23 = unpack2(cr23[s]);
        res[0] = fmaxf(res[0], F2arr[0] - 2.f * c01.x + P2n[s]);
        res[1] = fmaxf(res[1], F2arr[1] - 2.f * c01.y + P2n[s]);
        res[2] = fmaxf(res[2], F2arr[2] - 2.f * c23.x + P2n[s]);
        res[3] = fmaxf(res[3], F2arr[3] - 2.f * c23.y + P2n[s]);
    }

    int ph = ph0 + qy, pw = pw0 + qx;
    float* orow = out + (size_t)b * (Hn * Wn) + (ph << 1) * Wn + (pw << 1);
    *reinterpret_cast<float2*>(orow)      = make_float2(res[0], res[1]);
    *reinterpret_cast<float2*>(orow + Wn) = make_float2(res[2], res[3]);
}

// ---------------------------------------------------------------------------
extern "C" void kernel_launch(void* const* d_in, const int* in_sizes, int n_in,
                              void* d_out, int out_size) {
    const float* feat = (const float*)d_in[0];
    float* out = (float*)d_out;
    // dist is fixed at 1 by the problem's setup_inputs (d = 2)

    pool_kernel<<<16384, 256>>>(feat);
    dim3 g(8, 8, Bn);
    diff_kernel<<<g, 256>>>(feat, out);
}